// round 1
// baseline (speedup 1.0000x reference)
#include <cuda_runtime.h>
#include <mma.h>
#include <cstdint>
#include <cstddef>

using namespace nvcuda;

// Problem constants
#define BQ   32        // batch
#define SEQ  512       // sequence length (W)
#define INCH 512       // input channels (C*H)
#define HIDN 512       // hidden size
#define G4   2048      // 4*HID
#define MTOT (BQ*SEQ)  // 16384

// -------- scratch (static device allocations; no cudaMalloc allowed) --------
__device__ float g_xp[(size_t)2 * MTOT * G4];   // [dir][b*512+t][gate]  (256 MB)
__device__ float g_h[2][2][BQ * HIDN];          // [buf][dir][b*512+k]
__device__ unsigned g_bar_count;
__device__ unsigned g_bar_phase;

__device__ __forceinline__ float to_tf32(float x) {
    unsigned u;
    asm("cvt.rna.tf32.f32 %0, %1;" : "=r"(u) : "f"(x));
    return __uint_as_float(u);
}
__device__ __forceinline__ float sigmoidf_(float x) {
    return 1.0f / (1.0f + __expf(-x));
}

// ============================================================================
// Phase 1: xp[dir][m][g] = xs[m][:] @ W_ih[dir][g][:]^T + b_ih[g] + b_hh[g]
//   xs[m][k] = x[b][k][t] with m = b*512 + t  (x viewed as [B][512][512])
//   M = 16384, K = 512, N = 4096 (2 dirs * 2048)
//   Tiles: 128(M) x 64(N) x 16(K), 8 warps, warp tile 32x32, wmma tf32 16x16x8
// ============================================================================
__global__ void __launch_bounds__(256) gemm_xp_kernel(
    const float* __restrict__ x,
    const float* __restrict__ Wf, const float* __restrict__ Wb,
    const float* __restrict__ bihf, const float* __restrict__ bhhf,
    const float* __restrict__ bihb, const float* __restrict__ bhhb)
{
    __shared__ float sA[128 * 20];   // [m][k] row-major, ld 20
    __shared__ float sB[64 * 20];    // [n][k] -> col_major (k,n), ld 20
    __shared__ float sOut[128 * 64];
    __shared__ float sBias[64];

    const int tid = threadIdx.x;
    const int bn = blockIdx.x;            // 0..63  (N tiles over 4096)
    const int bm = blockIdx.y;            // 0..127 (M tiles over 16384)
    const int n0 = bn * 64;
    const int dir = n0 >> 11;
    const int g0 = n0 & 2047;
    const int m0 = bm * 128;
    const int b  = m0 >> 9;
    const int t0 = m0 & 511;

    const float* W   = dir ? Wb   : Wf;
    const float* bih = dir ? bihb : bihf;
    const float* bhh = dir ? bhhb : bhhf;
    if (tid < 64) sBias[tid] = bih[g0 + tid] + bhh[g0 + tid];

    const int w  = tid >> 5;
    const int wm = w >> 1;   // 0..3 -> m base wm*32
    const int wn = w & 1;    // 0..1 -> n base wn*32

    wmma::fragment<wmma::accumulator, 16, 16, 8, float> acc[2][2];
#pragma unroll
    for (int i = 0; i < 2; i++)
#pragma unroll
        for (int j = 0; j < 2; j++) wmma::fill_fragment(acc[i][j], 0.0f);

    const float* xb = x + (size_t)b * (512 * 512);  // [k][t]

    for (int k0 = 0; k0 < 512; k0 += 16) {
        __syncthreads();
        // Load A tile: 128 m x 16 k (coalesced along t=m)
#pragma unroll
        for (int i = 0; i < 8; i++) {
            int idx = i * 256 + tid;
            int mm = idx & 127, kk = idx >> 7;
            sA[mm * 20 + kk] = to_tf32(xb[(size_t)(k0 + kk) * 512 + t0 + mm]);
        }
        // Load B tile: 64 n x 16 k
#pragma unroll
        for (int i = 0; i < 4; i++) {
            int idx = i * 256 + tid;
            int kk = idx & 15, nn = idx >> 4;
            sB[nn * 20 + kk] = to_tf32(W[(size_t)(g0 + nn) * 512 + k0 + kk]);
        }
        __syncthreads();

#pragma unroll
        for (int ks = 0; ks < 16; ks += 8) {
            wmma::fragment<wmma::matrix_a, 16, 16, 8, wmma::precision::tf32, wmma::row_major> a0, a1;
            wmma::fragment<wmma::matrix_b, 16, 16, 8, wmma::precision::tf32, wmma::col_major> b0, b1;
            wmma::load_matrix_sync(a0, &sA[(wm * 32)      * 20 + ks], 20);
            wmma::load_matrix_sync(a1, &sA[(wm * 32 + 16) * 20 + ks], 20);
            wmma::load_matrix_sync(b0, &sB[(wn * 32)      * 20 + ks], 20);
            wmma::load_matrix_sync(b1, &sB[(wn * 32 + 16) * 20 + ks], 20);
            wmma::mma_sync(acc[0][0], a0, b0, acc[0][0]);
            wmma::mma_sync(acc[0][1], a0, b1, acc[0][1]);
            wmma::mma_sync(acc[1][0], a1, b0, acc[1][0]);
            wmma::mma_sync(acc[1][1], a1, b1, acc[1][1]);
        }
    }
    __syncthreads();
#pragma unroll
    for (int i = 0; i < 2; i++)
#pragma unroll
        for (int j = 0; j < 2; j++)
            wmma::store_matrix_sync(&sOut[(wm * 32 + i * 16) * 64 + wn * 32 + j * 16],
                                    acc[i][j], 64, wmma::mem_row_major);
    __syncthreads();

    float* xpd = g_xp + (size_t)dir * MTOT * G4 + (size_t)m0 * G4 + g0;
#pragma unroll
    for (int i = 0; i < 32; i++) {
        int idx = i * 256 + tid;
        int mm = idx >> 6, nn = idx & 63;
        xpd[(size_t)mm * G4 + nn] = sOut[mm * 64 + nn] + sBias[nn];
    }
}

// ============================================================================
// Phase 2: persistent recurrent kernel. 64 CTAs = 2 dirs * 32 slices.
//   CTA owns h-columns [slice*16, slice*16+16) -> 64 gate cols (16 from each
//   of i/f/g/o). W_hh slice (64x512, tf32) resident in SMEM.
//   Per step: stage h (32x512) from L2 double buffer, wmma GEMM 32x64x512
//   (2-way K-split across warps), fused LSTM elementwise, write h slice,
//   global sense-reversing barrier across all 64 CTAs.
// ============================================================================
#define NCTA2 64
#define LDW 516   // padded ld for sW / sH (bank-conflict avoidance)
#define LDG_ 68   // padded ld for gate staging
#define SW_FLOATS  (64 * LDW)
#define SH_FLOATS  (32 * LDW)
#define SG_FLOATS  (2 * 32 * LDG_)
#define SC_FLOATS  (512)
#define SMEM2_BYTES ((SW_FLOATS + SH_FLOATS + SG_FLOATS + SC_FLOATS) * 4)

__device__ __forceinline__ void grid_barrier() {
    __threadfence();
    __syncthreads();
    if (threadIdx.x == 0) {
        unsigned ph = *(volatile unsigned*)&g_bar_phase;
        unsigned old = atomicAdd(&g_bar_count, 1);
        if (old == NCTA2 - 1) {
            g_bar_count = 0;
            __threadfence();
            atomicExch(&g_bar_phase, ph + 1);
        } else {
            while (*(volatile unsigned*)&g_bar_phase == ph) { }
        }
    }
    __syncthreads();
}

__global__ void __launch_bounds__(256, 1) lstm_rec_kernel(
    const float* __restrict__ Whhf, const float* __restrict__ Whhb,
    float* __restrict__ out)
{
    extern __shared__ float smem[];
    float* sW = smem;                       // [64][LDW] (n-local rows x k)
    float* sH = sW + SW_FLOATS;             // [32][LDW]
    float* sG = sH + SH_FLOATS;             // [2][32][LDG_] k-split partials
    float* sC = sG + SG_FLOATS;             // [512] cell state

    const int tid   = threadIdx.x;
    const int dir   = blockIdx.x >> 5;
    const int slice = blockIdx.x & 31;
    const float* Whh = dir ? Whhb : Whhf;

    // Load W_hh slice (rounded to tf32). local row r = gb*16+q  ->  global row
    // gb*512 + slice*16 + q,  gb in {0..3} = i,f,g,o blocks.
#pragma unroll 4
    for (int i = 0; i < 128; i++) {
        int idx = i * 256 + tid;
        int kk = idx & 511, r = idx >> 9;
        int gb = r >> 4, q = r & 15;
        sW[r * LDW + kk] = to_tf32(Whh[(size_t)(gb * 512 + slice * 16 + q) * 512 + kk]);
    }
    // Zero cell state and our slice of h buffer 0
    sC[tid] = 0.0f; sC[tid + 256] = 0.0f;
#pragma unroll
    for (int i = 0; i < 2; i++) {
        int e = i * 256 + tid;          // 0..511
        int bb = e >> 4, q = e & 15;
        g_h[0][dir][bb * 512 + slice * 16 + q] = 0.0f;
    }
    grid_barrier();

    const int w  = tid >> 5;
    const int kw = w >> 2;       // 0..1 k-split half
    const int wi = w & 3;
    const int wm = wi >> 1;      // m base wm*16
    const int wn = wi & 1;       // n base wn*32

    const float* aBase  = &sH[(wm * 16) * LDW];
    const float* b0Base = &sW[(wn * 32) * LDW];
    const float* b1Base = &sW[(wn * 32 + 16) * LDW];
    const int k0 = kw * 256;

    for (int s = 0; s < 512; s++) {
        const int t  = dir ? (511 - s) : s;
        const int rb = s & 1;

        // Prefetch xp for our 2 elementwise elems (4 gates each) — long-latency
        // loads issued before the mma region.
        float xpv[2][4];
#pragma unroll
        for (int i = 0; i < 2; i++) {
            int e = i * 256 + tid;
            int bb = e >> 4, q = e & 15;
            const float* xr = g_xp + (size_t)dir * MTOT * G4
                              + (size_t)(bb * 512 + t) * G4 + slice * 16 + q;
            xpv[i][0] = xr[0];
            xpv[i][1] = xr[512];
            xpv[i][2] = xr[1024];
            xpv[i][3] = xr[1536];
        }

        // Stage full h (32x512 fp32) from L2 (must bypass L1: other SMs wrote it)
        const float4* hsrc = (const float4*)&g_h[rb][dir][0];
#pragma unroll
        for (int i = 0; i < 16; i++) {
            int idx4 = i * 256 + tid;         // 0..4095
            int fl = idx4 * 4;
            int bb = fl >> 9, kk = fl & 511;
            float4 v = __ldcg(hsrc + idx4);
            *(float4*)&sH[bb * LDW + kk] = v;
        }
        __syncthreads();

        // GEMM: gates_partial[kw] = h[:, k0:k0+256] @ W_slice[:, k0:k0+256]^T
        wmma::fragment<wmma::accumulator, 16, 16, 8, float> acc0, acc1;
        wmma::fill_fragment(acc0, 0.0f);
        wmma::fill_fragment(acc1, 0.0f);
#pragma unroll 4
        for (int kk = 0; kk < 256; kk += 8) {
            wmma::fragment<wmma::matrix_a, 16, 16, 8, wmma::precision::tf32, wmma::row_major> af;
            wmma::fragment<wmma::matrix_b, 16, 16, 8, wmma::precision::tf32, wmma::col_major> bf0, bf1;
            wmma::load_matrix_sync(af,  aBase  + k0 + kk, LDW);
            wmma::load_matrix_sync(bf0, b0Base + k0 + kk, LDW);
            wmma::load_matrix_sync(bf1, b1Base + k0 + kk, LDW);
            wmma::mma_sync(acc0, af, bf0, acc0);
            wmma::mma_sync(acc1, af, bf1, acc1);
        }
        wmma::store_matrix_sync(&sG[kw * (32 * LDG_) + (wm * 16) * LDG_ + wn * 32],      acc0, LDG_, wmma::mem_row_major);
        wmma::store_matrix_sync(&sG[kw * (32 * LDG_) + (wm * 16) * LDG_ + wn * 32 + 16], acc1, LDG_, wmma::mem_row_major);
        __syncthreads();

        // Fused LSTM elementwise: 512 elems (32 b x 16 q), 2 per thread
        float* hw = &g_h[1 - rb][dir][0];
#pragma unroll
        for (int i = 0; i < 2; i++) {
            int e = i * 256 + tid;
            int bb = e >> 4, q = e & 15;
            const float* g0p = &sG[bb * LDG_];
            const float* g1p = &sG[32 * LDG_ + bb * LDG_];
            float gi = g0p[q]      + g1p[q]      + xpv[i][0];
            float gf = g0p[16 + q] + g1p[16 + q] + xpv[i][1];
            float gg = g0p[32 + q] + g1p[32 + q] + xpv[i][2];
            float go = g0p[48 + q] + g1p[48 + q] + xpv[i][3];
            float c  = sC[e];
            float cn = sigmoidf_(gf) * c + sigmoidf_(gi) * tanhf(gg);
            float hn = sigmoidf_(go) * tanhf(cn);
            sC[e] = cn;
            __stcg(hw + bb * 512 + slice * 16 + q, to_tf32(hn));
            out[(size_t)(bb * 1024 + dir * 512 + slice * 16 + q) * 512 + t] = hn;
        }

        grid_barrier();   // h(t) globally visible before any CTA starts t+1
    }
}

// ============================================================================
extern "C" void kernel_launch(void* const* d_in, const int* in_sizes, int n_in,
                              void* d_out, int out_size)
{
    const float* x      = (const float*)d_in[0];
    const float* W_ih_f = (const float*)d_in[1];
    const float* W_hh_f = (const float*)d_in[2];
    const float* b_ih_f = (const float*)d_in[3];
    const float* b_hh_f = (const float*)d_in[4];
    const float* W_ih_b = (const float*)d_in[5];
    const float* W_hh_b = (const float*)d_in[6];
    const float* b_ih_b = (const float*)d_in[7];
    const float* b_hh_b = (const float*)d_in[8];
    float* out = (float*)d_out;

    cudaFuncSetAttribute(lstm_rec_kernel,
                         cudaFuncAttributeMaxDynamicSharedMemorySize, SMEM2_BYTES);

    dim3 g1(64, 128);   // 64 N-tiles (both dirs) x 128 M-tiles
    gemm_xp_kernel<<<g1, 256>>>(x, W_ih_f, W_ih_b, b_ih_f, b_hh_f, b_ih_b, b_hh_b);
    lstm_rec_kernel<<<NCTA2, 256, SMEM2_BYTES>>>(W_hh_f, W_hh_b, out);
}

// round 3
// speedup vs baseline: 1.0933x; 1.0933x over previous
#include <cuda_runtime.h>
#include <mma.h>
#include <cstdint>
#include <cstddef>

using namespace nvcuda;

#define BQ   32
#define SEQ  512
#define INCH 512
#define HIDN 512
#define G4   2048
#define MTOT (BQ*SEQ)

// -------- static device scratch --------
__device__ float g_xp[(size_t)2 * MTOT * G4];        // [dir][b*512+t][gate] 256MB
__device__ float g_h[2][2][BQ * HIDN];               // [buf][dir][b*512+k]
__device__ float g_hs[(size_t)2 * SEQ * BQ * HIDN];  // [dir][t][b*512+col] 64MB
__device__ unsigned g_flags[2][32][32];              // [dir][slice][pad] 128B apart
__device__ unsigned g_bar_count;
__device__ unsigned g_bar_phase;

__device__ __forceinline__ float to_tf32(float x) {
    unsigned u;
    asm("cvt.rna.tf32.f32 %0, %1;" : "=r"(u) : "f"(x));
    return __uint_as_float(u);
}
__device__ __forceinline__ float sigmoidf_(float x) {
    return 1.0f / (1.0f + __expf(-x));
}
__device__ __forceinline__ float tanh_fast(float x) {
    float y;
    asm("tanh.approx.f32 %0, %1;" : "=f"(y) : "f"(x));
    return y;
}

// ============================================================================
// Phase 1: xp = xs @ W_ih^T + b_ih + b_hh.   M=16384, K=512, N=4096.
// Tiles 128x64x32, 8 warps, A stored k-major (native x layout), reg dbl-buffer.
// ============================================================================
#define LDA1 144                 // stride for sA [32 k][128 m + pad]
#define LDB1 36                  // stride for sB [64 n][32 k + pad]
#define P1_POOL (128 * 68)       // sOut reuse: 8704 >= 32*144+64*36 = 6912

__global__ void __launch_bounds__(256) gemm_xp_kernel(
    const float* __restrict__ x,
    const float* __restrict__ Wf, const float* __restrict__ Wb,
    const float* __restrict__ bihf, const float* __restrict__ bhhf,
    const float* __restrict__ bihb, const float* __restrict__ bhhb)
{
    __shared__ float pool[P1_POOL];
    __shared__ float sBias[64];
    float* sA = pool;               // col-major A: elem (m,k) at sA[k*LDA1+m]
    float* sB = pool + 32 * LDA1;   // row-of-n B: elem (k,n) at sB[n*LDB1+k]

    const int tid = threadIdx.x;
    const int bn = blockIdx.x, bm = blockIdx.y;
    const int n0 = bn * 64;
    const int dir = n0 >> 11;
    const int g0 = n0 & 2047;
    const int m0 = bm * 128;
    const int b  = m0 >> 9;
    const int t0 = m0 & 511;

    const float* W   = dir ? Wb   : Wf;
    const float* bih = dir ? bihb : bihf;
    const float* bhh = dir ? bhhb : bhhf;
    if (tid < 64) sBias[tid] = bih[g0 + tid] + bhh[g0 + tid];

    const int w  = tid >> 5;
    const int wm = w >> 1;
    const int wn = w & 1;

    wmma::fragment<wmma::accumulator, 16, 16, 8, float> acc[2][2];
#pragma unroll
    for (int i = 0; i < 2; i++)
#pragma unroll
        for (int j = 0; j < 2; j++) wmma::fill_fragment(acc[i][j], 0.0f);

    const float* xb = x + (size_t)b * (512 * 512);   // [k][t]

    // loader indices (float offsets, scaled exactly once)
    const int kA  = tid >> 3;           // 0..31  (k row of A tile)
    const int mA  = (tid & 7) * 4;      // float offset base; +32*i per load
    const int nB  = tid >> 2;           // 0..63  (n row of B tile)
    const int kB  = (tid & 3) * 4;      // float offset base; +16*i per load

    float4 ra[4], rb2[2];
    {
        const float* src = xb + (size_t)kA * 512 + t0;
#pragma unroll
        for (int i = 0; i < 4; i++) ra[i] = *(const float4*)(src + mA + 32 * i);
        const float* ws = W + (size_t)(g0 + nB) * 512;
#pragma unroll
        for (int i = 0; i < 2; i++) rb2[i] = *(const float4*)(ws + kB + 16 * i);
    }

    for (int k0 = 0; k0 < 512; k0 += 32) {
        __syncthreads();
        // store current tile (with tf32 rounding)
#pragma unroll
        for (int i = 0; i < 4; i++) {
            float4 v = ra[i];
            float4 o = { to_tf32(v.x), to_tf32(v.y), to_tf32(v.z), to_tf32(v.w) };
            *(float4*)&sA[kA * LDA1 + mA + 32 * i] = o;
        }
#pragma unroll
        for (int i = 0; i < 2; i++) {
            float4 v = rb2[i];
            float4 o = { to_tf32(v.x), to_tf32(v.y), to_tf32(v.z), to_tf32(v.w) };
            *(float4*)&sB[nB * LDB1 + kB + 16 * i] = o;
        }
        __syncthreads();
        // prefetch next tile
        if (k0 + 32 < 512) {
            const float* src = xb + (size_t)(k0 + 32 + kA) * 512 + t0;
#pragma unroll
            for (int i = 0; i < 4; i++) ra[i] = *(const float4*)(src + mA + 32 * i);
            const float* ws = W + (size_t)(g0 + nB) * 512 + k0 + 32;
#pragma unroll
            for (int i = 0; i < 2; i++) rb2[i] = *(const float4*)(ws + kB + 16 * i);
        }
        // mma over the 32-k tile
#pragma unroll
        for (int kk = 0; kk < 32; kk += 8) {
            wmma::fragment<wmma::matrix_a, 16, 16, 8, wmma::precision::tf32, wmma::col_major> a0, a1;
            wmma::fragment<wmma::matrix_b, 16, 16, 8, wmma::precision::tf32, wmma::col_major> b0, b1;
            wmma::load_matrix_sync(a0, &sA[kk * LDA1 + wm * 32], LDA1);
            wmma::load_matrix_sync(a1, &sA[kk * LDA1 + wm * 32 + 16], LDA1);
            wmma::load_matrix_sync(b0, &sB[(wn * 32) * LDB1 + kk], LDB1);
            wmma::load_matrix_sync(b1, &sB[(wn * 32 + 16) * LDB1 + kk], LDB1);
            wmma::mma_sync(acc[0][0], a0, b0, acc[0][0]);
            wmma::mma_sync(acc[0][1], a0, b1, acc[0][1]);
            wmma::mma_sync(acc[1][0], a1, b0, acc[1][0]);
            wmma::mma_sync(acc[1][1], a1, b1, acc[1][1]);
        }
    }
    __syncthreads();
    float* sOut = pool;  // [128][68]
#pragma unroll
    for (int i = 0; i < 2; i++)
#pragma unroll
        for (int j = 0; j < 2; j++)
            wmma::store_matrix_sync(&sOut[(wm * 32 + i * 16) * 68 + wn * 32 + j * 16],
                                    acc[i][j], 68, wmma::mem_row_major);
    __syncthreads();

    float* xpd = g_xp + (size_t)dir * MTOT * G4 + (size_t)m0 * G4 + g0;
#pragma unroll
    for (int i = 0; i < 32; i++) {
        int idx = i * 256 + tid;
        int mm = idx >> 6, nn = idx & 63;
        xpd[(size_t)mm * G4 + nn] = sOut[mm * 68 + nn] + sBias[nn];
    }
}

// ============================================================================
// Phase 2: persistent recurrent kernel, 64 CTAs (2 dirs x 32 slices).
// Sync: per-direction producer flags (release/acquire), double-buffered h.
// ============================================================================
#define NCTA2 64
#define LDW 516
#define LDG_ 68
#define SW_FLOATS  (64 * LDW)
#define SH_FLOATS  (32 * LDW)
#define SG_FLOATS  (2 * 32 * LDG_)
#define SC_FLOATS  (512)
#define SMEM2_BYTES ((SW_FLOATS + SH_FLOATS + SG_FLOATS + SC_FLOATS) * 4)

__device__ __forceinline__ void grid_barrier_once() {
    __threadfence();
    __syncthreads();
    if (threadIdx.x == 0) {
        unsigned ph = *(volatile unsigned*)&g_bar_phase;
        unsigned old = atomicAdd(&g_bar_count, 1);
        if (old == NCTA2 - 1) {
            g_bar_count = 0;
            __threadfence();
            atomicExch(&g_bar_phase, ph + 1);
        } else {
            while (*(volatile unsigned*)&g_bar_phase == ph) { }
        }
    }
    __syncthreads();
}

__global__ void __launch_bounds__(256, 1) lstm_rec_kernel(
    const float* __restrict__ Whhf, const float* __restrict__ Whhb)
{
    extern __shared__ float smem[];
    float* sW = smem;
    float* sH = sW + SW_FLOATS;
    float* sG = sH + SH_FLOATS;
    float* sC = sG + SG_FLOATS;

    const int tid   = threadIdx.x;
    const int dir   = blockIdx.x >> 5;
    const int slice = blockIdx.x & 31;
    const float* Whh = dir ? Whhb : Whhf;

    // resident W_hh slice (tf32-rounded)
#pragma unroll 4
    for (int i = 0; i < 128; i++) {
        int idx = i * 256 + tid;
        int kk = idx & 511, r = idx >> 9;
        int gb = r >> 4, q = r & 15;
        sW[r * LDW + kk] = to_tf32(Whh[(size_t)(gb * 512 + slice * 16 + q) * 512 + kk]);
    }
    sC[tid] = 0.0f; sC[tid + 256] = 0.0f;
    // h(-1) = 0 into buf 1; reset own flag to 1 ("1 version written")
#pragma unroll
    for (int i = 0; i < 2; i++) {
        int e = i * 256 + tid;
        int bb = e >> 4, q = e & 15;
        __stcg(&g_h[1][dir][bb * 512 + slice * 16 + q], 0.0f);
    }
    if (tid == 0) g_flags[dir][slice][0] = 1u;
    grid_barrier_once();   // once per launch: orders resets/zeros across replays

    const int w  = tid >> 5;
    const int kw = w >> 2;
    const int wi = w & 3;
    const int wm = wi >> 1;
    const int wn = wi & 1;

    const float* aBase  = &sH[(wm * 16) * LDW];
    const float* b0Base = &sW[(wn * 32) * LDW];
    const float* b1Base = &sW[(wn * 32 + 16) * LDW];
    const int k0 = kw * 256;

    unsigned* myFlag = &g_flags[dir][slice][0];
    unsigned* pollFlag = (tid < 32) ? &g_flags[dir][tid][0] : &g_flags[dir][0][0];

    for (int s = 0; s < 512; s++) {
        const int t  = dir ? (511 - s) : s;
        const int rbR = (s + 1) & 1;   // read h(s-1)
        const int rbW = s & 1;         // write h(s)

        // xp prefetch (long latency, independent of flags)
        float xpv[2][4];
#pragma unroll
        for (int i = 0; i < 2; i++) {
            int e = i * 256 + tid;
            int bb = e >> 4, q = e & 15;
            const float* xr = g_xp + (size_t)dir * MTOT * G4
                              + (size_t)(bb * 512 + t) * G4 + slice * 16 + q;
            xpv[i][0] = __ldg(xr);
            xpv[i][1] = __ldg(xr + 512);
            xpv[i][2] = __ldg(xr + 1024);
            xpv[i][3] = __ldg(xr + 1536);
        }

        // wait for all producers of h(s-1): flag >= s+1
        if (tid < 32) {
            const unsigned target = (unsigned)(s + 1);
            unsigned v;
            do {
                asm volatile("ld.global.acquire.gpu.b32 %0, [%1];"
                             : "=r"(v) : "l"(pollFlag));
            } while (__any_sync(0xffffffffu, v < target));
        }
        __syncthreads();

        // stage h(s-1) from L2 into SMEM
        const float4* hsrc = (const float4*)&g_h[rbR][dir][0];
#pragma unroll
        for (int i = 0; i < 16; i++) {
            int idx4 = i * 256 + tid;
            int fl = idx4 * 4;
            int bb = fl >> 9, kk = fl & 511;
            float4 v = __ldcg(hsrc + idx4);
            *(float4*)&sH[bb * LDW + kk] = v;
        }
        __syncthreads();

        // GEMM 32x64x512 (k-split 2 across warps)
        wmma::fragment<wmma::accumulator, 16, 16, 8, float> acc0, acc1;
        wmma::fill_fragment(acc0, 0.0f);
        wmma::fill_fragment(acc1, 0.0f);
#pragma unroll 4
        for (int kk = 0; kk < 256; kk += 8) {
            wmma::fragment<wmma::matrix_a, 16, 16, 8, wmma::precision::tf32, wmma::row_major> af;
            wmma::fragment<wmma::matrix_b, 16, 16, 8, wmma::precision::tf32, wmma::col_major> bf0, bf1;
            wmma::load_matrix_sync(af,  aBase  + k0 + kk, LDW);
            wmma::load_matrix_sync(bf0, b0Base + k0 + kk, LDW);
            wmma::load_matrix_sync(bf1, b1Base + k0 + kk, LDW);
            wmma::mma_sync(acc0, af, bf0, acc0);
            wmma::mma_sync(acc1, af, bf1, acc1);
        }
        wmma::store_matrix_sync(&sG[kw * (32 * LDG_) + (wm * 16) * LDG_ + wn * 32],      acc0, LDG_, wmma::mem_row_major);
        wmma::store_matrix_sync(&sG[kw * (32 * LDG_) + (wm * 16) * LDG_ + wn * 32 + 16], acc1, LDG_, wmma::mem_row_major);
        __syncthreads();

        // fused LSTM elementwise
        float* hw  = &g_h[rbW][dir][0];
        float* hsw = &g_hs[(size_t)(dir * 512 + t) * (BQ * HIDN)];
#pragma unroll
        for (int i = 0; i < 2; i++) {
            int e = i * 256 + tid;
            int bb = e >> 4, q = e & 15;
            const float* g0p = &sG[bb * LDG_];
            const float* g1p = &sG[32 * LDG_ + bb * LDG_];
            float gi = g0p[q]      + g1p[q]      + xpv[i][0];
            float gf = g0p[16 + q] + g1p[16 + q] + xpv[i][1];
            float gg = g0p[32 + q] + g1p[32 + q] + xpv[i][2];
            float go = g0p[48 + q] + g1p[48 + q] + xpv[i][3];
            float c  = sC[e];
            float cn = sigmoidf_(gf) * c + sigmoidf_(gi) * tanh_fast(gg);
            float hn = sigmoidf_(go) * tanh_fast(cn);
            sC[e] = cn;
            __stcg(hw + bb * 512 + slice * 16 + q, to_tf32(hn));
            hsw[bb * 512 + slice * 16 + q] = hn;   // coalesced history write
        }

        // publish h(s): flag = s+2
        __threadfence();
        __syncthreads();
        if (tid == 0) {
            unsigned nv = (unsigned)(s + 2);
            asm volatile("st.global.release.gpu.b32 [%0], %1;" :: "l"(myFlag), "r"(nv));
        }
    }
}

// ============================================================================
// Phase 3: transpose h history [dir][t][b*512+col] -> out[(b*1024+dir*512+col)*512+t]
// ============================================================================
__global__ void __launch_bounds__(256) transpose_out_kernel(float* __restrict__ out)
{
    __shared__ float tile[32][33];
    const int tid = threadIdx.x;
    const int tx = tid & 31, ty = tid >> 5;     // ty 0..7
    const int ct = blockIdx.x;                   // col-tile 0..15
    const int tt = blockIdx.y;                   // t-tile 0..15
    const int z  = blockIdx.z;                   // dir*32+bb
    const int dir = z >> 5, bb = z & 31;
    const int col0 = ct * 32, t0 = tt * 32;

    const float* src = g_hs + (size_t)(dir * 512) * (BQ * HIDN) + bb * 512;
#pragma unroll
    for (int i = 0; i < 4; i++) {
        int tr = ty + 8 * i;
        tile[tr][tx] = src[(size_t)(t0 + tr) * (BQ * HIDN) + col0 + tx];
    }
    __syncthreads();
#pragma unroll
    for (int i = 0; i < 4; i++) {
        int cr = ty + 8 * i;
        out[(size_t)(bb * 1024 + dir * 512 + col0 + cr) * 512 + t0 + tx] = tile[tx][cr];
    }
}

// ============================================================================
extern "C" void kernel_launch(void* const* d_in, const int* in_sizes, int n_in,
                              void* d_out, int out_size)
{
    const float* x      = (const float*)d_in[0];
    const float* W_ih_f = (const float*)d_in[1];
    const float* W_hh_f = (const float*)d_in[2];
    const float* b_ih_f = (const float*)d_in[3];
    const float* b_hh_f = (const float*)d_in[4];
    const float* W_ih_b = (const float*)d_in[5];
    const float* W_hh_b = (const float*)d_in[6];
    const float* b_ih_b = (const float*)d_in[7];
    const float* b_hh_b = (const float*)d_in[8];
    float* out = (float*)d_out;

    cudaFuncSetAttribute(lstm_rec_kernel,
                         cudaFuncAttributeMaxDynamicSharedMemorySize, SMEM2_BYTES);

    dim3 g1(64, 128);
    gemm_xp_kernel<<<g1, 256>>>(x, W_ih_f, W_ih_b, b_ih_f, b_hh_f, b_ih_b, b_hh_b);
    lstm_rec_kernel<<<NCTA2, 256, SMEM2_BYTES>>>(W_hh_f, W_hh_b);
    dim3 g3(16, 16, 64);
    transpose_out_kernel<<<g3, 256>>>(out);
}